// round 15
// baseline (speedup 1.0000x reference)
#include <cuda_runtime.h>

#define Bb 32
#define Cc 3
#define Hh 512
#define Ww 512
#define NPIX (Hh*Ww)
#define CUTSZ 128
#define PARTS 16

#define TW 64
#define TH 32
#define SSTR 72                  // max src bbox width  (<= 70)
#define SROWS 45                 // max src bbox height (<= 44)
#define SPLANE (SSTR*SROWS)      // 3240 slots
#define AUG_SMEM (SPLANE*12)     // float2 rg plane + float b plane = 38880 B

// Scratch (no allocations allowed)
__device__ float g_part[Bb*Cc*PARTS];
__device__ float g_mean[Bb*Cc];
__device__ unsigned g_cnt[Bb*Cc];   // zero-init at load; self-resetting

// ---------------------------------------------------------------------------
// Kernel 1: per-(b,c) partial sums of clip(img + bf, -1, 1).
// Last block per plane finalizes the mean (deterministic fixed-order sum).
// ---------------------------------------------------------------------------
__global__ void __launch_bounds__(128) mean_partial(const float* __restrict__ img,
                                                    const float* __restrict__ u_bright)
{
    int bc   = blockIdx.x / PARTS;
    int part = blockIdx.x % PARTS;
    int b    = bc / Cc;
    float bf = (u_bright[b] * 2.0f - 1.0f) * 0.2f;

    const float4* p = (const float4*)(img + (size_t)bc * NPIX + (size_t)part * (NPIX / PARTS));
    int t = threadIdx.x;
    float s0 = 0.0f, s1 = 0.0f, s2 = 0.0f, s3 = 0.0f;
#pragma unroll 2
    for (int i = 0; i < 32; i += 4) {
        float4 v0 = p[t + (i + 0) * 128];
        float4 v1 = p[t + (i + 1) * 128];
        float4 v2 = p[t + (i + 2) * 128];
        float4 v3 = p[t + (i + 3) * 128];
        s0 += fminf(v0.x + bf, 1.0f) + fminf(v0.y + bf, 1.0f)
            + fminf(v0.z + bf, 1.0f) + fminf(v0.w + bf, 1.0f);
        s1 += fminf(v1.x + bf, 1.0f) + fminf(v1.y + bf, 1.0f)
            + fminf(v1.z + bf, 1.0f) + fminf(v1.w + bf, 1.0f);
        s2 += fminf(v2.x + bf, 1.0f) + fminf(v2.y + bf, 1.0f)
            + fminf(v2.z + bf, 1.0f) + fminf(v2.w + bf, 1.0f);
        s3 += fminf(v3.x + bf, 1.0f) + fminf(v3.y + bf, 1.0f)
            + fminf(v3.z + bf, 1.0f) + fminf(v3.w + bf, 1.0f);
    }
    float s = (s0 + s1) + (s2 + s3);
#pragma unroll
    for (int o = 16; o > 0; o >>= 1) s += __shfl_xor_sync(0xffffffffu, s, o);
    __shared__ float sh[4];
    if ((t & 31) == 0) sh[t >> 5] = s;
    __syncthreads();
    if (t == 0) {
        g_part[blockIdx.x] = (sh[0] + sh[1]) + (sh[2] + sh[3]);
        __threadfence();
        unsigned old = atomicAdd(&g_cnt[bc], 1u);
        if (old == PARTS - 1) {
            float tot = 0.0f;
#pragma unroll
            for (int k = 0; k < PARTS; k++) tot += __ldcg(&g_part[bc * PARTS + k]);
            g_mean[bc] = tot * (1.0f / (float)NPIX);
            __threadfence();
            atomicExch(&g_cnt[bc], 0u);   // reset for next graph replay
        }
    }
}

// ---------------------------------------------------------------------------
// Per-pixel color transform (fused brightness+contrast; select-free sat/rcp).
// ---------------------------------------------------------------------------
__device__ __forceinline__ float3 color_xform(
    float r, float g, float bl, float cf,
    float bfcr, float capr, float bfcg, float capg, float bfcb, float capb,
    float dh, float sf)
{
    float cr = fminf(fmaf(r,  cf, bfcr), capr);
    float cg = fminf(fmaf(g,  cf, bfcg), capg);
    float cb = fminf(fmaf(bl, cf, bfcb), capb);

    float mx = fmaxf(cr, fmaxf(cg, cb));
    float mn = fminf(cr, fminf(cg, cb));
    float d  = mx - mn;
    // d==0: invd6 huge but all numerators are exactly 0 -> matches safe_d path
    float invd6;
    asm("rcp.approx.f32 %0, %1;" : "=f"(invd6) : "f"(fmaxf(d * 6.0f, 1e-30f)));

    float hr = (cg - cb) * invd6;
    hr = (cg < cb) ? hr + 1.0f : hr;                 // mod-360 wrap
    float hg = fmaf(cb - cr, invd6, 2.0f / 6.0f);
    float hb = fmaf(cr - cg, invd6, 4.0f / 6.0f);
    float hch = (mx == cb) ? hb : ((mx == cg) ? hg : hr);

    float c  = fmaxf(fminf(d * sf, mx), 0.0f);       // == (mx>0? min(d*sf,mx):0)
    float hp = fminf(fmaxf(hch + dh, 0.0f), 1.0f);

    float t6 = hp * 6.0f;
    float kr = __saturatef(fabsf(t6 - 3.0f) - 1.0f);
    kr = (hp == 1.0f) ? 0.0f : kr;                   // ref: h==1 -> gray
    float kg = __saturatef(2.0f - fabsf(t6 - 2.0f));
    float kb = __saturatef(2.0f - fabsf(t6 - 4.0f));
    float m  = mx - c;
    return make_float3(fmaf(c, kr, m), fmaf(c, kg, m), fmaf(c, kb, m));
}

// ---------------------------------------------------------------------------
// Sampling inner body, compile-time cutout switch.
// Incremental grid coords (adds only), serial-FMA blends, cheap weights.
// ---------------------------------------------------------------------------
template<bool CUT>
__device__ __forceinline__ void sample_tile(
    const float2* __restrict__ smrg, const float* __restrict__ smb,
    const float* __restrict__ noise, float* __restrict__ out,
    int b, int w0, int h0, int tx, int ty,
    float gxw, float gxh, float gxc, float gyw, float gyh, float gyc,
    int sbase, int cx, int cy)
{
    // Per-thread base coordinate; other 3 pixels derived by constant adds.
    float gx0 = fmaf(gxw, (float)(w0 + tx), fmaf(gxh, (float)(h0 + ty), gxc));
    float gy0 = fmaf(gyw, (float)(w0 + tx), fmaf(gyh, (float)(h0 + ty), gyc));
    float dxgx = 32.0f * gxw, dxgy = 32.0f * gyw;   // +32 in w
    float dygx = 16.0f * gxh, dygy = 16.0f * gyh;   // +16 in h

#pragma unroll
    for (int dy = 0; dy < 2; dy++) {
        int h = h0 + ty + dy * 16;
        bool rowcut = CUT && ((unsigned)(h - cy) < (unsigned)CUTSZ);
        size_t orow = (size_t)b * Cc * NPIX + (size_t)h * Ww;
        float gxr = dy ? (gx0 + dygx) : gx0;
        float gyr = dy ? (gy0 + dygy) : gy0;
#pragma unroll
        for (int dx = 0; dx < 2; dx++) {
            int w = w0 + tx + dx * 32;
            float gxp = dx ? (gxr + dxgx) : gxr;
            float gyp = dx ? (gyr + dxgy) : gyr;

            size_t o = orow + w;
            float nr = __ldcs(noise + o);
            float ng = __ldcs(noise + o + NPIX);
            float nb = __ldcs(noise + o + 2 * NPIX);

            float x0f = floorf(gxp), y0f = floorf(gyp);
            float wx = gxp - x0f, wy = gyp - y0f;
            int x0 = (int)x0f, y0 = (int)y0f;

            float w11 = wx * wy;
            float w01 = wx - w11;
            float w10 = wy - w11;
            float w00 = (1.0f - wx) - w10;

            int si = y0 * SSTR + x0 - sbase;

            float2 v00 = smrg[si];
            float2 v01 = smrg[si + 1];
            float2 v10 = smrg[si + SSTR];
            float2 v11 = smrg[si + SSTR + 1];
            float b00 = smb[si];
            float b01 = smb[si + 1];
            float b10 = smb[si + SSTR];
            float b11 = smb[si + SSTR + 1];

            float accr = fmaf(v00.x, w00, fmaf(v01.x, w01, fmaf(v10.x, w10, v11.x * w11)));
            float accg = fmaf(v00.y, w00, fmaf(v01.y, w01, fmaf(v10.y, w10, v11.y * w11)));
            float accb = fmaf(b00,   w00, fmaf(b01,   w01, fmaf(b10,   w10, b11   * w11)));

            accr = fminf(fmaxf(fmaf(nr, 0.05f, accr), -1.0f), 1.0f);
            accg = fminf(fmaxf(fmaf(ng, 0.05f, accg), -1.0f), 1.0f);
            accb = fminf(fmaxf(fmaf(nb, 0.05f, accb), -1.0f), 1.0f);

            if (CUT) {
                bool cut = rowcut && ((unsigned)(w - cx) < (unsigned)CUTSZ);
                if (cut) { accr = 0.0f; accg = 0.0f; accb = 0.0f; }
            }

            __stcs(out + o,            accr);
            __stcs(out + o + NPIX,     accg);
            __stcs(out + o + 2 * NPIX, accb);
        }
    }
}

// ---------------------------------------------------------------------------
// Kernel 2: smem-tiled; 4 blocks/SM; exact-width fill via magic division;
// interior tiles skip bounds checks entirely (block-uniform branch).
// ---------------------------------------------------------------------------
__global__ void __launch_bounds__(512, 4) aug_kernel(
    const float* __restrict__ img,
    const float* __restrict__ u_bright,
    const float* __restrict__ u_contrast,
    const float* __restrict__ u_hue,
    const float* __restrict__ u_sat,
    const float* __restrict__ u_angle,
    const float* __restrict__ noise,
    const int*   __restrict__ cutout_xy,
    const int*   __restrict__ cutout_apply,
    float*       __restrict__ out)
{
    extern __shared__ char smraw[];
    float2* smrg = (float2*)smraw;                       // SPLANE float2
    float*  smb  = (float*)(smraw + SPLANE * 8);         // SPLANE float

    int b  = blockIdx.z;
    int w0 = blockIdx.x * TW;
    int h0 = blockIdx.y * TH;
    int t  = threadIdx.x;

    float bf  = (u_bright[b]   * 2.0f - 1.0f) * 0.2f;
    float cf  = 1.0f + (u_contrast[b] * 2.0f - 1.0f) * 0.2f;
    float dh  = (u_hue[b]      * 2.0f - 1.0f) * 0.1f;
    float sf  = 1.0f + (u_sat[b]      * 2.0f - 1.0f) * 0.2f;
    float ang = (u_angle[b]    * 2.0f - 1.0f) * 0.17453292519943295f;
    float sa, ca;
    sincosf(ang, &sa, &ca);
    float omcf = 1.0f - cf;
    float mrc  = g_mean[b * 3 + 0] * omcf;
    float mgc  = g_mean[b * 3 + 1] * omcf;
    float mbc  = g_mean[b * 3 + 2] * omcf;
    float bfcr = fmaf(bf, cf, mrc), capr = fminf(cf + mrc, 1.0f);
    float bfcg = fmaf(bf, cf, mgc), capg = fminf(cf + mgc, 1.0f);
    float bfcb = fmaf(bf, cf, mbc), capb = fminf(cf + mbc, 1.0f);

    const float s2 = 2.0f / 511.0f;
    float gxw = 256.0f * s2 * ca;
    float gxh = -256.0f * s2 * sa;
    float gxc = 256.0f * (1.0f - ca + sa) - 0.5f;
    float gyw = 256.0f * s2 * sa;
    float gyh = 256.0f * s2 * ca;
    float gyc = 256.0f * (1.0f - sa - ca) - 0.5f;

    float xxl = fmaf((float)w0,            s2, -1.0f);
    float xxh = fmaf((float)(w0 + TW - 1), s2, -1.0f);
    float yyl = fmaf((float)h0,            s2, -1.0f);
    float yyh = fmaf((float)(h0 + TH - 1), s2, -1.0f);

    float gx00 = ca * xxl - sa * yyl, gx01 = ca * xxh - sa * yyl;
    float gx10 = ca * xxl - sa * yyh, gx11 = ca * xxh - sa * yyh;
    float gy00 = sa * xxl + ca * yyl, gy01 = sa * xxh + ca * yyl;
    float gy10 = sa * xxl + ca * yyh, gy11 = sa * xxh + ca * yyh;

    float pxmin = fminf(fminf(gx00, gx01), fminf(gx10, gx11));
    float pxmax = fmaxf(fmaxf(gx00, gx01), fmaxf(gx10, gx11));
    float pymin = fminf(fminf(gy00, gy01), fminf(gy10, gy11));
    float pymax = fmaxf(fmaxf(gy00, gy01), fmaxf(gy10, gy11));

    int xs = (int)floorf((pxmin + 1.0f) * 256.0f - 0.5f);
    int xe = (int)floorf((pxmax + 1.0f) * 256.0f - 0.5f) + 1;
    int ys = (int)floorf((pymin + 1.0f) * 256.0f - 0.5f);
    int ye = (int)floorf((pymax + 1.0f) * 256.0f - 0.5f) + 1;
    int sw = xe - xs + 1; if (sw > SSTR)  sw = SSTR;
    int sh = ye - ys + 1; if (sh > SROWS) sh = SROWS;
    int sbase = ys * SSTR + xs;

    // Exact-width fill: i -> (ly,lx) via magic division (exact for i < 2^16)
    unsigned magic = 0xFFFFFFFFu / (unsigned)sw + 1u;
    int total = sw * sh;
    const float* base = img + (size_t)b * Cc * NPIX;
    bool interior = (xs >= 0) && (ys >= 0) && (xs + sw <= Ww) && (ys + sh <= Hh);

    if (interior) {
        // Every bbox pixel is in-image: no bounds checks, no zero-init.
#pragma unroll 2
        for (int i = t; i < total; i += 512) {
            int ly = (int)__umulhi((unsigned)i, magic);
            int lx = i - ly * sw;
            int off = (Hh - 1 - (ys + ly)) * Ww + (xs + lx);   // vertical flip
            float r  = __ldg(base + off);
            float g  = __ldg(base + NPIX + off);
            float bl = __ldg(base + 2 * NPIX + off);
            float3 c = color_xform(r, g, bl, cf, bfcr, capr, bfcg, capg,
                                   bfcb, capb, dh, sf);
            int si = ly * SSTR + lx;
            smrg[si] = make_float2(c.x, c.y);
            smb[si]  = c.z;
        }
    } else {
#pragma unroll 2
        for (int i = t; i < total; i += 512) {
            int ly = (int)__umulhi((unsigned)i, magic);
            int lx = i - ly * sw;
            int xi = xs + lx;
            int yi = ys + ly;
            float3 c = make_float3(0.0f, 0.0f, 0.0f);
            if (((unsigned)xi < (unsigned)Ww) && ((unsigned)yi < (unsigned)Hh)) {
                int off = (Hh - 1 - yi) * Ww + xi;
                float r  = __ldg(base + off);
                float g  = __ldg(base + NPIX + off);
                float bl = __ldg(base + 2 * NPIX + off);
                c = color_xform(r, g, bl, cf, bfcr, capr, bfcg, capg,
                                bfcb, capb, dh, sf);
            }
            int si = ly * SSTR + lx;
            smrg[si] = make_float2(c.x, c.y);
            smb[si]  = c.z;
        }
    }
    __syncthreads();

    int tx = t & 31;        // 0..31
    int ty = t >> 5;        // 0..15

    int cx = cutout_xy[b * 2 + 0];
    int cy = cutout_xy[b * 2 + 1];
    bool overlap = (cutout_apply[b] != 0) &&
                   (cx < w0 + TW) && (cx + CUTSZ > w0) &&
                   (cy < h0 + TH) && (cy + CUTSZ > h0);

    if (overlap) {
        sample_tile<true >(smrg, smb, noise, out, b, w0, h0, tx, ty,
                           gxw, gxh, gxc, gyw, gyh, gyc, sbase, cx, cy);
    } else {
        sample_tile<false>(smrg, smb, noise, out, b, w0, h0, tx, ty,
                           gxw, gxh, gxc, gyw, gyh, gyc, sbase, cx, cy);
    }
}

// ---------------------------------------------------------------------------
extern "C" void kernel_launch(void* const* d_in, const int* in_sizes, int n_in,
                              void* d_out, int out_size)
{
    const float* img        = (const float*)d_in[0];
    const float* u_bright   = (const float*)d_in[1];
    const float* u_contrast = (const float*)d_in[2];
    const float* u_hue      = (const float*)d_in[3];
    const float* u_sat      = (const float*)d_in[4];
    const float* u_angle    = (const float*)d_in[5];
    const float* noise      = (const float*)d_in[6];
    const int*   cutout_xy  = (const int*)d_in[7];
    const int*   cutout_ap  = (const int*)d_in[8];
    float* out = (float*)d_out;

    cudaFuncSetAttribute(aug_kernel, cudaFuncAttributeMaxDynamicSharedMemorySize, AUG_SMEM);

    mean_partial<<<Bb * Cc * PARTS, 128>>>(img, u_bright);

    dim3 grd(Ww / TW, Hh / TH, Bb);
    aug_kernel<<<grd, 512, AUG_SMEM>>>(img, u_bright, u_contrast, u_hue, u_sat,
                                       u_angle, noise, cutout_xy, cutout_ap, out);
}

// round 16
// speedup vs baseline: 1.0039x; 1.0039x over previous
#include <cuda_runtime.h>

#define Bb 32
#define Cc 3
#define Hh 512
#define Ww 512
#define NPIX (Hh*Ww)
#define CUTSZ 128
#define PARTS 16

#define TW 64
#define TH 32
#define SSTR 72                  // max src bbox width  (<= 70)
#define SROWS 45                 // max src bbox height (<= 44)
#define SPLANE (SSTR*SROWS)      // 3240 slots
#define AUG_SMEM (SPLANE*12)     // float2 rg plane + float b plane = 38880 B

// Scratch (no allocations allowed)
__device__ float g_part[Bb*Cc*PARTS];
__device__ float g_mean[Bb*Cc];
__device__ unsigned g_cnt[Bb*Cc];   // zero-init at load; self-resetting

// ---------------------------------------------------------------------------
// Kernel 1: per-(b,c) partial sums of clip(img + bf, -1, 1).
// unroll 4 -> 16 independent LDG.128 in flight (MLP for DRAM latency hiding).
// Last block per plane finalizes the mean (deterministic fixed-order sum).
// ---------------------------------------------------------------------------
__global__ void __launch_bounds__(128) mean_partial(const float* __restrict__ img,
                                                    const float* __restrict__ u_bright)
{
    int bc   = blockIdx.x / PARTS;
    int part = blockIdx.x % PARTS;
    int b    = bc / Cc;
    float bf = (u_bright[b] * 2.0f - 1.0f) * 0.2f;

    const float4* p = (const float4*)(img + (size_t)bc * NPIX + (size_t)part * (NPIX / PARTS));
    int t = threadIdx.x;
    float s0 = 0.0f, s1 = 0.0f, s2 = 0.0f, s3 = 0.0f;
#pragma unroll 4
    for (int i = 0; i < 32; i += 4) {
        float4 v0 = p[t + (i + 0) * 128];
        float4 v1 = p[t + (i + 1) * 128];
        float4 v2 = p[t + (i + 2) * 128];
        float4 v3 = p[t + (i + 3) * 128];
        s0 += fminf(v0.x + bf, 1.0f) + fminf(v0.y + bf, 1.0f)
            + fminf(v0.z + bf, 1.0f) + fminf(v0.w + bf, 1.0f);
        s1 += fminf(v1.x + bf, 1.0f) + fminf(v1.y + bf, 1.0f)
            + fminf(v1.z + bf, 1.0f) + fminf(v1.w + bf, 1.0f);
        s2 += fminf(v2.x + bf, 1.0f) + fminf(v2.y + bf, 1.0f)
            + fminf(v2.z + bf, 1.0f) + fminf(v2.w + bf, 1.0f);
        s3 += fminf(v3.x + bf, 1.0f) + fminf(v3.y + bf, 1.0f)
            + fminf(v3.z + bf, 1.0f) + fminf(v3.w + bf, 1.0f);
    }
    float s = (s0 + s1) + (s2 + s3);
#pragma unroll
    for (int o = 16; o > 0; o >>= 1) s += __shfl_xor_sync(0xffffffffu, s, o);
    __shared__ float sh[4];
    if ((t & 31) == 0) sh[t >> 5] = s;
    __syncthreads();
    if (t == 0) {
        g_part[blockIdx.x] = (sh[0] + sh[1]) + (sh[2] + sh[3]);
        __threadfence();
        unsigned old = atomicAdd(&g_cnt[bc], 1u);
        if (old == PARTS - 1) {
            float tot = 0.0f;
#pragma unroll
            for (int k = 0; k < PARTS; k++) tot += __ldcg(&g_part[bc * PARTS + k]);
            g_mean[bc] = tot * (1.0f / (float)NPIX);
            __threadfence();
            atomicExch(&g_cnt[bc], 0u);   // reset for next graph replay
        }
    }
}

// ---------------------------------------------------------------------------
// Per-pixel color transform (fused brightness+contrast; select-free sat/rcp).
// Per channel: x2 = min(fma(x, cf, bfc_ch), cap_ch)  [lower clips proven dead]
// ---------------------------------------------------------------------------
__device__ __forceinline__ float3 color_xform(
    float r, float g, float bl, float cf,
    float bfcr, float capr, float bfcg, float capg, float bfcb, float capb,
    float dh, float sf)
{
    float cr = fminf(fmaf(r,  cf, bfcr), capr);
    float cg = fminf(fmaf(g,  cf, bfcg), capg);
    float cb = fminf(fmaf(bl, cf, bfcb), capb);

    float mx = fmaxf(cr, fmaxf(cg, cb));
    float mn = fminf(cr, fminf(cg, cb));
    float d  = mx - mn;
    // d==0: invd6 huge but all numerators are exactly 0 -> matches safe_d path
    float invd6;
    asm("rcp.approx.f32 %0, %1;" : "=f"(invd6) : "f"(fmaxf(d * 6.0f, 1e-30f)));

    float hr = (cg - cb) * invd6;
    hr = (cg < cb) ? hr + 1.0f : hr;                 // mod-360 wrap
    float hg = fmaf(cb - cr, invd6, 2.0f / 6.0f);
    float hb = fmaf(cr - cg, invd6, 4.0f / 6.0f);
    float hch = (mx == cb) ? hb : ((mx == cg) ? hg : hr);

    float c  = fmaxf(fminf(d * sf, mx), 0.0f);       // == (mx>0? min(d*sf,mx):0)
    float hp = fminf(fmaxf(hch + dh, 0.0f), 1.0f);

    float t6 = hp * 6.0f;
    float kr = __saturatef(fabsf(t6 - 3.0f) - 1.0f);
    kr = (hp == 1.0f) ? 0.0f : kr;                   // ref: h==1 -> gray
    float kg = __saturatef(2.0f - fabsf(t6 - 2.0f));
    float kb = __saturatef(2.0f - fabsf(t6 - 4.0f));
    float m  = mx - c;
    return make_float3(fmaf(c, kr, m), fmaf(c, kg, m), fmaf(c, kb, m));
}

// ---------------------------------------------------------------------------
// Sampling inner body, compile-time cutout switch (R14 proven form).
// float2 (r,g) plane + float b plane: 12 L1 phases/px, lane-adjacent.
// ---------------------------------------------------------------------------
template<bool CUT>
__device__ __forceinline__ void sample_tile(
    const float2* __restrict__ smrg, const float* __restrict__ smb,
    const float* __restrict__ noise, float* __restrict__ out,
    int b, int w0, int h0, int tx, int ty,
    float gxw, float gxh, float gxc, float gyw, float gyh, float gyc,
    int sbase, int cx, int cy)
{
#pragma unroll
    for (int dy = 0; dy < 2; dy++) {
        int h = h0 + ty + dy * 16;
        bool rowcut = CUT && ((unsigned)(h - cy) < (unsigned)CUTSZ);
        size_t orow = (size_t)b * Cc * NPIX + (size_t)h * Ww;
        float gxrow = fmaf(gxh, (float)h, gxc);
        float gyrow = fmaf(gyh, (float)h, gyc);
#pragma unroll
        for (int dx = 0; dx < 2; dx++) {
            int w = w0 + tx + dx * 32;

            size_t o = orow + w;
            float nr = __ldcs(noise + o);
            float ng = __ldcs(noise + o + NPIX);
            float nb = __ldcs(noise + o + 2 * NPIX);

            float gxp = fmaf(gxw, (float)w, gxrow);
            float gyp = fmaf(gyw, (float)w, gyrow);
            float x0f = floorf(gxp), y0f = floorf(gyp);
            float wx = gxp - x0f, wy = gyp - y0f;
            int x0 = (int)x0f, y0 = (int)y0f;

            float w11 = wy * wx;
            float w10 = wy - w11;
            float w01 = wx - w11;
            float w00 = 1.0f - wy - wx + w11;

            int si = y0 * SSTR + x0 - sbase;

            float2 v00 = smrg[si];
            float2 v01 = smrg[si + 1];
            float2 v10 = smrg[si + SSTR];
            float2 v11 = smrg[si + SSTR + 1];
            float b00 = smb[si];
            float b01 = smb[si + 1];
            float b10 = smb[si + SSTR];
            float b11 = smb[si + SSTR + 1];

            float accr = fmaf(v00.x, w00, v01.x * w01) + fmaf(v10.x, w10, v11.x * w11);
            float accg = fmaf(v00.y, w00, v01.y * w01) + fmaf(v10.y, w10, v11.y * w11);
            float accb = fmaf(b00,   w00, b01   * w01) + fmaf(b10,   w10, b11   * w11);

            accr = fminf(fmaxf(fmaf(nr, 0.05f, accr), -1.0f), 1.0f);
            accg = fminf(fmaxf(fmaf(ng, 0.05f, accg), -1.0f), 1.0f);
            accb = fminf(fmaxf(fmaf(nb, 0.05f, accb), -1.0f), 1.0f);

            if (CUT) {
                bool cut = rowcut && ((unsigned)(w - cx) < (unsigned)CUTSZ);
                if (cut) { accr = 0.0f; accg = 0.0f; accb = 0.0f; }
            }

            __stcs(out + o,            accr);
            __stcs(out + o + NPIX,     accg);
            __stcs(out + o + 2 * NPIX, accb);
        }
    }
}

// ---------------------------------------------------------------------------
// Kernel 2: smem-tiled; 4 blocks/SM; exact-width fill via magic division;
// interior tiles skip bounds checks entirely (block-uniform branch).
// ---------------------------------------------------------------------------
__global__ void __launch_bounds__(512, 4) aug_kernel(
    const float* __restrict__ img,
    const float* __restrict__ u_bright,
    const float* __restrict__ u_contrast,
    const float* __restrict__ u_hue,
    const float* __restrict__ u_sat,
    const float* __restrict__ u_angle,
    const float* __restrict__ noise,
    const int*   __restrict__ cutout_xy,
    const int*   __restrict__ cutout_apply,
    float*       __restrict__ out)
{
    extern __shared__ char smraw[];
    float2* smrg = (float2*)smraw;                       // SPLANE float2
    float*  smb  = (float*)(smraw + SPLANE * 8);         // SPLANE float

    int b  = blockIdx.z;
    int w0 = blockIdx.x * TW;
    int h0 = blockIdx.y * TH;
    int t  = threadIdx.x;

    float bf  = (u_bright[b]   * 2.0f - 1.0f) * 0.2f;
    float cf  = 1.0f + (u_contrast[b] * 2.0f - 1.0f) * 0.2f;
    float dh  = (u_hue[b]      * 2.0f - 1.0f) * 0.1f;
    float sf  = 1.0f + (u_sat[b]      * 2.0f - 1.0f) * 0.2f;
    float ang = (u_angle[b]    * 2.0f - 1.0f) * 0.17453292519943295f;
    float sa, ca;
    sincosf(ang, &sa, &ca);
    float omcf = 1.0f - cf;
    float mrc  = g_mean[b * 3 + 0] * omcf;
    float mgc  = g_mean[b * 3 + 1] * omcf;
    float mbc  = g_mean[b * 3 + 2] * omcf;
    float bfcr = fmaf(bf, cf, mrc), capr = fminf(cf + mrc, 1.0f);
    float bfcg = fmaf(bf, cf, mgc), capg = fminf(cf + mgc, 1.0f);
    float bfcb = fmaf(bf, cf, mbc), capb = fminf(cf + mbc, 1.0f);

    const float s2 = 2.0f / 511.0f;
    float gxw = 256.0f * s2 * ca;
    float gxh = -256.0f * s2 * sa;
    float gxc = 256.0f * (1.0f - ca + sa) - 0.5f;
    float gyw = 256.0f * s2 * sa;
    float gyh = 256.0f * s2 * ca;
    float gyc = 256.0f * (1.0f - sa - ca) - 0.5f;

    float xxl = fmaf((float)w0,            s2, -1.0f);
    float xxh = fmaf((float)(w0 + TW - 1), s2, -1.0f);
    float yyl = fmaf((float)h0,            s2, -1.0f);
    float yyh = fmaf((float)(h0 + TH - 1), s2, -1.0f);

    float gx00 = ca * xxl - sa * yyl, gx01 = ca * xxh - sa * yyl;
    float gx10 = ca * xxl - sa * yyh, gx11 = ca * xxh - sa * yyh;
    float gy00 = sa * xxl + ca * yyl, gy01 = sa * xxh + ca * yyl;
    float gy10 = sa * xxl + ca * yyh, gy11 = sa * xxh + ca * yyh;

    float pxmin = fminf(fminf(gx00, gx01), fminf(gx10, gx11));
    float pxmax = fmaxf(fmaxf(gx00, gx01), fmaxf(gx10, gx11));
    float pymin = fminf(fminf(gy00, gy01), fminf(gy10, gy11));
    float pymax = fmaxf(fmaxf(gy00, gy01), fmaxf(gy10, gy11));

    int xs = (int)floorf((pxmin + 1.0f) * 256.0f - 0.5f);
    int xe = (int)floorf((pxmax + 1.0f) * 256.0f - 0.5f) + 1;
    int ys = (int)floorf((pymin + 1.0f) * 256.0f - 0.5f);
    int ye = (int)floorf((pymax + 1.0f) * 256.0f - 0.5f) + 1;
    int sw = xe - xs + 1; if (sw > SSTR)  sw = SSTR;
    int sh = ye - ys + 1; if (sh > SROWS) sh = SROWS;
    int sbase = ys * SSTR + xs;

    // Exact-width fill: i -> (ly,lx) via magic division (exact for i < 2^16)
    unsigned magic = 0xFFFFFFFFu / (unsigned)sw + 1u;
    int total = sw * sh;
    const float* base = img + (size_t)b * Cc * NPIX;
    bool interior = (xs >= 0) && (ys >= 0) && (xs + sw <= Ww) && (ys + sh <= Hh);

    if (interior) {
        // Every bbox pixel is in-image: no bounds checks, no zero-init.
#pragma unroll 2
        for (int i = t; i < total; i += 512) {
            int ly = (int)__umulhi((unsigned)i, magic);
            int lx = i - ly * sw;
            int off = (Hh - 1 - (ys + ly)) * Ww + (xs + lx);   // vertical flip
            float r  = __ldg(base + off);
            float g  = __ldg(base + NPIX + off);
            float bl = __ldg(base + 2 * NPIX + off);
            float3 c = color_xform(r, g, bl, cf, bfcr, capr, bfcg, capg,
                                   bfcb, capb, dh, sf);
            int si = ly * SSTR + lx;
            smrg[si] = make_float2(c.x, c.y);
            smb[si]  = c.z;
        }
    } else {
#pragma unroll 2
        for (int i = t; i < total; i += 512) {
            int ly = (int)__umulhi((unsigned)i, magic);
            int lx = i - ly * sw;
            int xi = xs + lx;
            int yi = ys + ly;
            float3 c = make_float3(0.0f, 0.0f, 0.0f);
            if (((unsigned)xi < (unsigned)Ww) && ((unsigned)yi < (unsigned)Hh)) {
                int off = (Hh - 1 - yi) * Ww + xi;
                float r  = __ldg(base + off);
                float g  = __ldg(base + NPIX + off);
                float bl = __ldg(base + 2 * NPIX + off);
                c = color_xform(r, g, bl, cf, bfcr, capr, bfcg, capg,
                                bfcb, capb, dh, sf);
            }
            int si = ly * SSTR + lx;
            smrg[si] = make_float2(c.x, c.y);
            smb[si]  = c.z;
        }
    }
    __syncthreads();

    int tx = t & 31;        // 0..31
    int ty = t >> 5;        // 0..15

    int cx = cutout_xy[b * 2 + 0];
    int cy = cutout_xy[b * 2 + 1];
    bool overlap = (cutout_apply[b] != 0) &&
                   (cx < w0 + TW) && (cx + CUTSZ > w0) &&
                   (cy < h0 + TH) && (cy + CUTSZ > h0);

    if (overlap) {
        sample_tile<true >(smrg, smb, noise, out, b, w0, h0, tx, ty,
                           gxw, gxh, gxc, gyw, gyh, gyc, sbase, cx, cy);
    } else {
        sample_tile<false>(smrg, smb, noise, out, b, w0, h0, tx, ty,
                           gxw, gxh, gxc, gyw, gyh, gyc, sbase, cx, cy);
    }
}

// ---------------------------------------------------------------------------
extern "C" void kernel_launch(void* const* d_in, const int* in_sizes, int n_in,
                              void* d_out, int out_size)
{
    const float* img        = (const float*)d_in[0];
    const float* u_bright   = (const float*)d_in[1];
    const float* u_contrast = (const float*)d_in[2];
    const float* u_hue      = (const float*)d_in[3];
    const float* u_sat      = (const float*)d_in[4];
    const float* u_angle    = (const float*)d_in[5];
    const float* noise      = (const float*)d_in[6];
    const int*   cutout_xy  = (const int*)d_in[7];
    const int*   cutout_ap  = (const int*)d_in[8];
    float* out = (float*)d_out;

    cudaFuncSetAttribute(aug_kernel, cudaFuncAttributeMaxDynamicSharedMemorySize, AUG_SMEM);

    mean_partial<<<Bb * Cc * PARTS, 128>>>(img, u_bright);

    dim3 grd(Ww / TW, Hh / TH, Bb);
    aug_kernel<<<grd, 512, AUG_SMEM>>>(img, u_bright, u_contrast, u_hue, u_sat,
                                       u_angle, noise, cutout_xy, cutout_ap, out);
}

// round 17
// speedup vs baseline: 1.0465x; 1.0424x over previous
#include <cuda_runtime.h>

#define Bb 32
#define Cc 3
#define Hh 512
#define Ww 512
#define NPIX (Hh*Ww)
#define CUTSZ 128
#define PARTS 16

#define TW 64
#define TH 32
#define SSTR 72                  // max src bbox width  (<= 70)
#define SROWS 45                 // max src bbox height (<= 44)
#define SPLANE (SSTR*SROWS)      // 3240 slots
#define AUG_SMEM (SPLANE*12)     // float2 rg plane + float b plane = 38880 B

// Scratch (no allocations allowed)
__device__ float g_part[Bb*Cc*PARTS];
__device__ float g_mean[Bb*Cc];
__device__ unsigned g_cnt[Bb*Cc];   // zero-init at load; self-resetting

// ---------------------------------------------------------------------------
// Kernel 1: per-(b,c) partial sums of clip(img + bf, -1, 1).
// Last block per plane finalizes the mean (deterministic fixed-order sum).
// ---------------------------------------------------------------------------
__global__ void __launch_bounds__(128) mean_partial(const float* __restrict__ img,
                                                    const float* __restrict__ u_bright)
{
    int bc   = blockIdx.x / PARTS;
    int part = blockIdx.x % PARTS;
    int b    = bc / Cc;
    float bf = (u_bright[b] * 2.0f - 1.0f) * 0.2f;

    const float4* p = (const float4*)(img + (size_t)bc * NPIX + (size_t)part * (NPIX / PARTS));
    int t = threadIdx.x;
    float s0 = 0.0f, s1 = 0.0f, s2 = 0.0f, s3 = 0.0f;
#pragma unroll 2
    for (int i = 0; i < 32; i += 4) {
        float4 v0 = p[t + (i + 0) * 128];
        float4 v1 = p[t + (i + 1) * 128];
        float4 v2 = p[t + (i + 2) * 128];
        float4 v3 = p[t + (i + 3) * 128];
        s0 += fminf(v0.x + bf, 1.0f) + fminf(v0.y + bf, 1.0f)
            + fminf(v0.z + bf, 1.0f) + fminf(v0.w + bf, 1.0f);
        s1 += fminf(v1.x + bf, 1.0f) + fminf(v1.y + bf, 1.0f)
            + fminf(v1.z + bf, 1.0f) + fminf(v1.w + bf, 1.0f);
        s2 += fminf(v2.x + bf, 1.0f) + fminf(v2.y + bf, 1.0f)
            + fminf(v2.z + bf, 1.0f) + fminf(v2.w + bf, 1.0f);
        s3 += fminf(v3.x + bf, 1.0f) + fminf(v3.y + bf, 1.0f)
            + fminf(v3.z + bf, 1.0f) + fminf(v3.w + bf, 1.0f);
    }
    float s = (s0 + s1) + (s2 + s3);
#pragma unroll
    for (int o = 16; o > 0; o >>= 1) s += __shfl_xor_sync(0xffffffffu, s, o);
    __shared__ float sh[4];
    if ((t & 31) == 0) sh[t >> 5] = s;
    __syncthreads();
    if (t == 0) {
        g_part[blockIdx.x] = (sh[0] + sh[1]) + (sh[2] + sh[3]);
        __threadfence();
        unsigned old = atomicAdd(&g_cnt[bc], 1u);
        if (old == PARTS - 1) {
            float tot = 0.0f;
#pragma unroll
            for (int k = 0; k < PARTS; k++) tot += __ldcg(&g_part[bc * PARTS + k]);
            g_mean[bc] = tot * (1.0f / (float)NPIX);
            __threadfence();
            atomicExch(&g_cnt[bc], 0u);   // reset for next graph replay
        }
    }
}

// ---------------------------------------------------------------------------
// Per-pixel color transform (fused brightness+contrast; select-free sat/rcp).
// ---------------------------------------------------------------------------
__device__ __forceinline__ float3 color_xform(
    float r, float g, float bl, float cf,
    float bfcr, float capr, float bfcg, float capg, float bfcb, float capb,
    float dh, float sf)
{
    float cr = fminf(fmaf(r,  cf, bfcr), capr);
    float cg = fminf(fmaf(g,  cf, bfcg), capg);
    float cb = fminf(fmaf(bl, cf, bfcb), capb);

    float mx = fmaxf(cr, fmaxf(cg, cb));
    float mn = fminf(cr, fminf(cg, cb));
    float d  = mx - mn;
    // d==0: invd6 huge but all numerators are exactly 0 -> matches safe_d path
    float invd6;
    asm("rcp.approx.f32 %0, %1;" : "=f"(invd6) : "f"(fmaxf(d * 6.0f, 1e-30f)));

    float hr = (cg - cb) * invd6;
    hr = (cg < cb) ? hr + 1.0f : hr;                 // mod-360 wrap
    float hg = fmaf(cb - cr, invd6, 2.0f / 6.0f);
    float hb = fmaf(cr - cg, invd6, 4.0f / 6.0f);
    float hch = (mx == cb) ? hb : ((mx == cg) ? hg : hr);

    float c  = fmaxf(fminf(d * sf, mx), 0.0f);       // == (mx>0? min(d*sf,mx):0)
    float hp = fminf(fmaxf(hch + dh, 0.0f), 1.0f);

    float t6 = hp * 6.0f;
    float kr = __saturatef(fabsf(t6 - 3.0f) - 1.0f);
    kr = (hp == 1.0f) ? 0.0f : kr;                   // ref: h==1 -> gray
    float kg = __saturatef(2.0f - fabsf(t6 - 2.0f));
    float kb = __saturatef(2.0f - fabsf(t6 - 4.0f));
    float m  = mx - c;
    return make_float3(fmaf(c, kr, m), fmaf(c, kg, m), fmaf(c, kb, m));
}

// ---------------------------------------------------------------------------
// Sampling inner body, compile-time cutout switch.
// Cross-pixel software pipeline: noise for px j+1 is loaded during px j's
// LDS + blend work. Offsets between the 4 pixels are compile-time constants.
// ---------------------------------------------------------------------------
template<bool CUT>
__device__ __forceinline__ void sample_tile(
    const float2* __restrict__ smrg, const float* __restrict__ smb,
    const float* __restrict__ noise, float* __restrict__ out,
    int b, int w0, int h0, int tx, int ty,
    float gxw, float gxh, float gxc, float gyw, float gyh, float gyc,
    int sbase, int cx, int cy)
{
    const int wbase = w0 + tx;
    const int hbase = h0 + ty;
    const size_t o0 = (size_t)b * Cc * NPIX + (size_t)hbase * Ww + wbase;
    // pixel j: dw = (j&1)*32, dh = (j>>1)*16; offset delta vs o0:
    //   j=0:0, j=1:32, j=2:16*Ww, j=3:16*Ww+32

    // Prefetch noise for pixel 0
    float nr = __ldcs(noise + o0);
    float ng = __ldcs(noise + o0 + NPIX);
    float nb = __ldcs(noise + o0 + 2 * NPIX);

#pragma unroll
    for (int j = 0; j < 4; j++) {
        const int dwj = (j & 1) * 32;
        const int dhj = (j >> 1) * 16;
        const size_t oj = o0 + (size_t)dhj * Ww + dwj;

        // Prefetch noise for pixel j+1 (overlaps with this pixel's work)
        float nr2 = 0.0f, ng2 = 0.0f, nb2 = 0.0f;
        if (j < 3) {
            const int dwn = ((j + 1) & 1) * 32;
            const int dhn = ((j + 1) >> 1) * 16;
            const size_t on = o0 + (size_t)dhn * Ww + dwn;
            nr2 = __ldcs(noise + on);
            ng2 = __ldcs(noise + on + NPIX);
            nb2 = __ldcs(noise + on + 2 * NPIX);
        }

        int w = wbase + dwj;
        int h = hbase + dhj;

        float gxp = fmaf(gxw, (float)w, fmaf(gxh, (float)h, gxc));
        float gyp = fmaf(gyw, (float)w, fmaf(gyh, (float)h, gyc));
        float x0f = floorf(gxp), y0f = floorf(gyp);
        float wx = gxp - x0f, wy = gyp - y0f;
        int x0 = (int)x0f, y0 = (int)y0f;

        float w11 = wy * wx;
        float w10 = wy - w11;
        float w01 = wx - w11;
        float w00 = 1.0f - wy - wx + w11;

        int si = y0 * SSTR + x0 - sbase;

        float2 v00 = smrg[si];
        float2 v01 = smrg[si + 1];
        float2 v10 = smrg[si + SSTR];
        float2 v11 = smrg[si + SSTR + 1];
        float b00 = smb[si];
        float b01 = smb[si + 1];
        float b10 = smb[si + SSTR];
        float b11 = smb[si + SSTR + 1];

        float accr = fmaf(v00.x, w00, v01.x * w01) + fmaf(v10.x, w10, v11.x * w11);
        float accg = fmaf(v00.y, w00, v01.y * w01) + fmaf(v10.y, w10, v11.y * w11);
        float accb = fmaf(b00,   w00, b01   * w01) + fmaf(b10,   w10, b11   * w11);

        accr = fminf(fmaxf(fmaf(nr, 0.05f, accr), -1.0f), 1.0f);
        accg = fminf(fmaxf(fmaf(ng, 0.05f, accg), -1.0f), 1.0f);
        accb = fminf(fmaxf(fmaf(nb, 0.05f, accb), -1.0f), 1.0f);

        if (CUT) {
            bool cut = ((unsigned)(h - cy) < (unsigned)CUTSZ) &&
                       ((unsigned)(w - cx) < (unsigned)CUTSZ);
            if (cut) { accr = 0.0f; accg = 0.0f; accb = 0.0f; }
        }

        __stcs(out + oj,            accr);
        __stcs(out + oj + NPIX,     accg);
        __stcs(out + oj + 2 * NPIX, accb);

        nr = nr2; ng = ng2; nb = nb2;
    }
}

// ---------------------------------------------------------------------------
// Kernel 2: smem-tiled; 4 blocks/SM; exact-width fill via magic division;
// interior tiles skip bounds checks entirely (block-uniform branch).
// ---------------------------------------------------------------------------
__global__ void __launch_bounds__(512, 4) aug_kernel(
    const float* __restrict__ img,
    const float* __restrict__ u_bright,
    const float* __restrict__ u_contrast,
    const float* __restrict__ u_hue,
    const float* __restrict__ u_sat,
    const float* __restrict__ u_angle,
    const float* __restrict__ noise,
    const int*   __restrict__ cutout_xy,
    const int*   __restrict__ cutout_apply,
    float*       __restrict__ out)
{
    extern __shared__ char smraw[];
    float2* smrg = (float2*)smraw;                       // SPLANE float2
    float*  smb  = (float*)(smraw + SPLANE * 8);         // SPLANE float

    int b  = blockIdx.z;
    int w0 = blockIdx.x * TW;
    int h0 = blockIdx.y * TH;
    int t  = threadIdx.x;

    float bf  = (u_bright[b]   * 2.0f - 1.0f) * 0.2f;
    float cf  = 1.0f + (u_contrast[b] * 2.0f - 1.0f) * 0.2f;
    float dh  = (u_hue[b]      * 2.0f - 1.0f) * 0.1f;
    float sf  = 1.0f + (u_sat[b]      * 2.0f - 1.0f) * 0.2f;
    float ang = (u_angle[b]    * 2.0f - 1.0f) * 0.17453292519943295f;
    float sa, ca;
    sincosf(ang, &sa, &ca);
    float omcf = 1.0f - cf;
    float mrc  = g_mean[b * 3 + 0] * omcf;
    float mgc  = g_mean[b * 3 + 1] * omcf;
    float mbc  = g_mean[b * 3 + 2] * omcf;
    float bfcr = fmaf(bf, cf, mrc), capr = fminf(cf + mrc, 1.0f);
    float bfcg = fmaf(bf, cf, mgc), capg = fminf(cf + mgc, 1.0f);
    float bfcb = fmaf(bf, cf, mbc), capb = fminf(cf + mbc, 1.0f);

    const float s2 = 2.0f / 511.0f;
    float gxw = 256.0f * s2 * ca;
    float gxh = -256.0f * s2 * sa;
    float gxc = 256.0f * (1.0f - ca + sa) - 0.5f;
    float gyw = 256.0f * s2 * sa;
    float gyh = 256.0f * s2 * ca;
    float gyc = 256.0f * (1.0f - sa - ca) - 0.5f;

    float xxl = fmaf((float)w0,            s2, -1.0f);
    float xxh = fmaf((float)(w0 + TW - 1), s2, -1.0f);
    float yyl = fmaf((float)h0,            s2, -1.0f);
    float yyh = fmaf((float)(h0 + TH - 1), s2, -1.0f);

    float gx00 = ca * xxl - sa * yyl, gx01 = ca * xxh - sa * yyl;
    float gx10 = ca * xxl - sa * yyh, gx11 = ca * xxh - sa * yyh;
    float gy00 = sa * xxl + ca * yyl, gy01 = sa * xxh + ca * yyl;
    float gy10 = sa * xxl + ca * yyh, gy11 = sa * xxh + ca * yyh;

    float pxmin = fminf(fminf(gx00, gx01), fminf(gx10, gx11));
    float pxmax = fmaxf(fmaxf(gx00, gx01), fmaxf(gx10, gx11));
    float pymin = fminf(fminf(gy00, gy01), fminf(gy10, gy11));
    float pymax = fmaxf(fmaxf(gy00, gy01), fmaxf(gy10, gy11));

    int xs = (int)floorf((pxmin + 1.0f) * 256.0f - 0.5f);
    int xe = (int)floorf((pxmax + 1.0f) * 256.0f - 0.5f) + 1;
    int ys = (int)floorf((pymin + 1.0f) * 256.0f - 0.5f);
    int ye = (int)floorf((pymax + 1.0f) * 256.0f - 0.5f) + 1;
    int sw = xe - xs + 1; if (sw > SSTR)  sw = SSTR;
    int sh = ye - ys + 1; if (sh > SROWS) sh = SROWS;
    int sbase = ys * SSTR + xs;

    // Exact-width fill: i -> (ly,lx) via magic division (exact for i < 2^16)
    unsigned magic = 0xFFFFFFFFu / (unsigned)sw + 1u;
    int total = sw * sh;
    const float* base = img + (size_t)b * Cc * NPIX;
    bool interior = (xs >= 0) && (ys >= 0) && (xs + sw <= Ww) && (ys + sh <= Hh);

    if (interior) {
        // Every bbox pixel is in-image: no bounds checks, no zero-init.
#pragma unroll 2
        for (int i = t; i < total; i += 512) {
            int ly = (int)__umulhi((unsigned)i, magic);
            int lx = i - ly * sw;
            int off = (Hh - 1 - (ys + ly)) * Ww + (xs + lx);   // vertical flip
            float r  = __ldg(base + off);
            float g  = __ldg(base + NPIX + off);
            float bl = __ldg(base + 2 * NPIX + off);
            float3 c = color_xform(r, g, bl, cf, bfcr, capr, bfcg, capg,
                                   bfcb, capb, dh, sf);
            int si = ly * SSTR + lx;
            smrg[si] = make_float2(c.x, c.y);
            smb[si]  = c.z;
        }
    } else {
#pragma unroll 2
        for (int i = t; i < total; i += 512) {
            int ly = (int)__umulhi((unsigned)i, magic);
            int lx = i - ly * sw;
            int xi = xs + lx;
            int yi = ys + ly;
            float3 c = make_float3(0.0f, 0.0f, 0.0f);
            if (((unsigned)xi < (unsigned)Ww) && ((unsigned)yi < (unsigned)Hh)) {
                int off = (Hh - 1 - yi) * Ww + xi;
                float r  = __ldg(base + off);
                float g  = __ldg(base + NPIX + off);
                float bl = __ldg(base + 2 * NPIX + off);
                c = color_xform(r, g, bl, cf, bfcr, capr, bfcg, capg,
                                bfcb, capb, dh, sf);
            }
            int si = ly * SSTR + lx;
            smrg[si] = make_float2(c.x, c.y);
            smb[si]  = c.z;
        }
    }
    __syncthreads();

    int tx = t & 31;        // 0..31
    int ty = t >> 5;        // 0..15

    int cx = cutout_xy[b * 2 + 0];
    int cy = cutout_xy[b * 2 + 1];
    bool overlap = (cutout_apply[b] != 0) &&
                   (cx < w0 + TW) && (cx + CUTSZ > w0) &&
                   (cy < h0 + TH) && (cy + CUTSZ > h0);

    if (overlap) {
        sample_tile<true >(smrg, smb, noise, out, b, w0, h0, tx, ty,
                           gxw, gxh, gxc, gyw, gyh, gyc, sbase, cx, cy);
    } else {
        sample_tile<false>(smrg, smb, noise, out, b, w0, h0, tx, ty,
                           gxw, gxh, gxc, gyw, gyh, gyc, sbase, cx, cy);
    }
}

// ---------------------------------------------------------------------------
extern "C" void kernel_launch(void* const* d_in, const int* in_sizes, int n_in,
                              void* d_out, int out_size)
{
    const float* img        = (const float*)d_in[0];
    const float* u_bright   = (const float*)d_in[1];
    const float* u_contrast = (const float*)d_in[2];
    const float* u_hue      = (const float*)d_in[3];
    const float* u_sat      = (const float*)d_in[4];
    const float* u_angle    = (const float*)d_in[5];
    const float* noise      = (const float*)d_in[6];
    const int*   cutout_xy  = (const int*)d_in[7];
    const int*   cutout_ap  = (const int*)d_in[8];
    float* out = (float*)d_out;

    cudaFuncSetAttribute(aug_kernel, cudaFuncAttributeMaxDynamicSharedMemorySize, AUG_SMEM);

    mean_partial<<<Bb * Cc * PARTS, 128>>>(img, u_bright);

    dim3 grd(Ww / TW, Hh / TH, Bb);
    aug_kernel<<<grd, 512, AUG_SMEM>>>(img, u_bright, u_contrast, u_hue, u_sat,
                                       u_angle, noise, cutout_xy, cutout_ap, out);
}